// round 11
// baseline (speedup 1.0000x reference)
#include <cuda_runtime.h>
#include <cstddef>
#include <cstdint>

// Problem constants
#define BB 8
#define TT 2048
#define DD 1024
#define HH 8
#define NN 32
#define MROWS (BB*TT)          // 16384
#define HN (HH*NN)             // 256

// ---------------------------------------------------------------------------
// Scratch (no cudaMalloc allowed) — __device__ globals.
// Split planes: packed bf16 pairs (one u32 = 2 bf16 along K).
// ---------------------------------------------------------------------------
__device__ unsigned g_xh [(size_t)MROWS * DD / 2];
__device__ unsigned g_xl [(size_t)MROWS * DD / 2];
__device__ unsigned g_xph[(size_t)MROWS * DD / 2];
__device__ unsigned g_xpl[(size_t)MROWS * DD / 2];
__device__ unsigned g_wih[(size_t)DD * DD / 2];
__device__ unsigned g_wil[(size_t)DD * DD / 2];
__device__ unsigned g_wkh[(size_t)HN * DD / 2];
__device__ unsigned g_wkl[(size_t)HN * DD / 2];
__device__ unsigned g_wvh[(size_t)HN * DD / 2];
__device__ unsigned g_wvl[(size_t)HN * DD / 2];
__device__ unsigned g_wqh[(size_t)HN * DD / 2];
__device__ unsigned g_wql[(size_t)HN * DD / 2];
__device__ unsigned g_wbh[(size_t)HN * DD / 2];
__device__ unsigned g_wbl[(size_t)HN * DD / 2];
__device__ unsigned g_woh[(size_t)DD * HN / 2];
__device__ unsigned g_wol[(size_t)DD * HN / 2];
__device__ float    g_k   [(size_t)MROWS * HN];
__device__ float    g_v   [(size_t)MROWS * HN];
__device__ float    g_q   [(size_t)MROWS * HN];
__device__ float    g_beta[(size_t)MROWS * HN];
__device__ unsigned short g_cellh[(size_t)MROWS * HN];
__device__ unsigned short g_celll[(size_t)MROWS * HN];

// ---------------------------------------------------------------------------
// bf16 split helpers
// ---------------------------------------------------------------------------
__device__ __forceinline__ float trunc_hi(float x) {
    return __uint_as_float(__float_as_uint(x) & 0xFFFF0000u);
}
__device__ __forceinline__ unsigned pack_hi_pair(float e0, float e1) {
    return __byte_perm(__float_as_uint(e0), __float_as_uint(e1), 0x7632);
}
__device__ __forceinline__ unsigned pack_lo_pair(float l0, float l1) {
    unsigned d;
    asm("cvt.rn.bf16x2.f32 %0, %1, %2;" : "=r"(d) : "f"(l1), "f"(l0));
    return d;
}

__global__ void __launch_bounds__(256)
split_kernel(const float2* __restrict__ in, unsigned* __restrict__ hi,
             unsigned* __restrict__ lo, int n)
{
    const int i = blockIdx.x * 256 + threadIdx.x;
    if (i < n) {
        const float2 v = in[i];
        hi[i] = pack_hi_pair(v.x, v.y);
        lo[i] = pack_lo_pair(v.x - trunc_hi(v.x), v.y - trunc_hi(v.y));
    }
}

__device__ __forceinline__ void mma_bf16(float d[4],
                                         unsigned a0, unsigned a1,
                                         unsigned a2, unsigned a3,
                                         unsigned b0, unsigned b1) {
    asm("mma.sync.aligned.m16n8k16.row.col.f32.bf16.bf16.f32 "
        "{%0,%1,%2,%3}, {%4,%5,%6,%7}, {%8,%9}, {%0,%1,%2,%3};"
        : "+f"(d[0]), "+f"(d[1]), "+f"(d[2]), "+f"(d[3])
        : "r"(a0), "r"(a1), "r"(a2), "r"(a3), "r"(b0), "r"(b1));
}

__device__ __forceinline__ void ldsm4(unsigned& r0, unsigned& r1,
                                      unsigned& r2, unsigned& r3, unsigned addr) {
    asm volatile("ldmatrix.sync.aligned.m8n8.x4.shared.b16 {%0,%1,%2,%3}, [%4];"
                 : "=r"(r0), "=r"(r1), "=r"(r2), "=r"(r3) : "r"(addr));
}

// ---------------------------------------------------------------------------
// bf16x2-compensated tensor GEMM on pre-split operands.
// C = epi( A @ W^T ). Block tile 256(M) x 128(N), chunk k16 (8 u32 words),
// 8 warps as 4M x 2N -> warp tile 64x64. Per chunk per warp:
// 16 ldmatrix.x4 + 96 HMMA  (1.5x more HMMA per LDS byte than 64x32).
// epi: 0 identity(f32), 2 sigmoid(acc+bias), 3 head-band row-norm,
//      4 silu + split-write
// ---------------------------------------------------------------------------
#define PLW 12
#define APLANE (256 * PLW)          // u32 per A plane
#define WPLANE (128 * PLW)          // u32 per W plane
#define BUFW (2 * APLANE + 2 * WPLANE)   // u32 per stage buffer (9216)
#define SMEM_GB (2 * BUFW * 4)           // 73728 bytes

__device__ __forceinline__ void mma_gemm_core(
    const unsigned* __restrict__ Ah, const unsigned* __restrict__ Al,
    const unsigned* __restrict__ Wh, const unsigned* __restrict__ Wl,
    float* __restrict__ C, unsigned* __restrict__ Chi, unsigned* __restrict__ Clo,
    const float* __restrict__ bias,
    int epi, int Nout, int Kw, int row0, int col0)
{
    extern __shared__ unsigned sm[];   // [2][BUFW]

    const int tid  = threadIdx.x;
    const int wid  = tid >> 5;
    const int lane = tid & 31;
    const int g    = lane >> 2;
    const int c    = lane & 3;
    const int wm   = (wid & 3) * 64;   // warp M offset (0..192)
    const int wn   = (wid >> 2) * 64;  // warp N offset (0 or 64)

    // staging: A row = tid (8 words), W row = tid>>1 (4 words, half = tid&1)
    const unsigned* ApH = Ah + (size_t)(row0 + tid) * Kw;
    const unsigned* ApL = Al + (size_t)(row0 + tid) * Kw;
    const int wrow = tid >> 1;
    const int whalf = (tid & 1) * 4;
    const unsigned* WpH = Wh + (size_t)(col0 + wrow) * Kw + whalf;
    const unsigned* WpL = Wl + (size_t)(col0 + wrow) * Kw + whalf;
    const int sa = tid * PLW;              // A smem row base (u32)
    const int swr = wrow * PLW + whalf;    // W smem row base (u32)

    const unsigned smb = (unsigned)__cvta_generic_to_shared(&sm[0]);
    const unsigned aoff = (((lane & 15) * PLW) + ((lane >> 4) << 2)) * 4;
    const unsigned boff = ((((lane >> 4) * 8 + (lane & 7)) * PLW) + ((lane & 8) ? 4 : 0)) * 4;

    float acc[4][8][4];
#pragma unroll
    for (int mt = 0; mt < 4; ++mt)
#pragma unroll
        for (int nt = 0; nt < 8; ++nt)
#pragma unroll
            for (int e = 0; e < 4; ++e) acc[mt][nt][e] = 0.f;

    const int nchunks = Kw / 8;

    // prologue: stage chunk 0 into buffer 0
    {
        *reinterpret_cast<uint4*>(&sm[0 * APLANE + sa])     = *reinterpret_cast<const uint4*>(ApH);
        *reinterpret_cast<uint4*>(&sm[0 * APLANE + sa + 4]) = *reinterpret_cast<const uint4*>(ApH + 4);
        *reinterpret_cast<uint4*>(&sm[1 * APLANE + sa])     = *reinterpret_cast<const uint4*>(ApL);
        *reinterpret_cast<uint4*>(&sm[1 * APLANE + sa + 4]) = *reinterpret_cast<const uint4*>(ApL + 4);
        *reinterpret_cast<uint4*>(&sm[2 * APLANE + swr])          = *reinterpret_cast<const uint4*>(WpH);
        *reinterpret_cast<uint4*>(&sm[2 * APLANE + WPLANE + swr]) = *reinterpret_cast<const uint4*>(WpL);
    }
    __syncthreads();

    for (int chunk = 0; chunk < nchunks; ++chunk) {
        const int cur = chunk & 1;
        const bool more = (chunk + 1 < nchunks);

        uint4 fa0, fa1, fl0, fl1, fwh, fwl;
        if (more) {
            const int ko = (chunk + 1) * 8;
            fa0 = *reinterpret_cast<const uint4*>(ApH + ko);
            fa1 = *reinterpret_cast<const uint4*>(ApH + ko + 4);
            fl0 = *reinterpret_cast<const uint4*>(ApL + ko);
            fl1 = *reinterpret_cast<const uint4*>(ApL + ko + 4);
            fwh = *reinterpret_cast<const uint4*>(WpH + ko);
            fwl = *reinterpret_cast<const uint4*>(WpL + ko);
        }

        const unsigned pb = smb + (unsigned)cur * (BUFW * 4);

        // B fragments: 4 nt-pairs x (hi, lo)  (warp N band = 64 cols)
        unsigned bh[4][4], bl[4][4];
#pragma unroll
        for (int pr = 0; pr < 4; ++pr) {
            const unsigned ba = pb + (2 * APLANE) * 4 + (unsigned)(wn + pr * 16) * PLW * 4 + boff;
            ldsm4(bh[pr][0], bh[pr][1], bh[pr][2], bh[pr][3], ba);
            ldsm4(bl[pr][0], bl[pr][1], bl[pr][2], bl[pr][3], ba + WPLANE * 4);
        }

#pragma unroll
        for (int mt = 0; mt < 4; ++mt) {
            unsigned ah[4], al[4];
            const unsigned aa = pb + (unsigned)(wm + mt * 16) * PLW * 4 + aoff;
            ldsm4(ah[0], ah[1], ah[2], ah[3], aa);
            ldsm4(al[0], al[1], al[2], al[3], aa + APLANE * 4);
#pragma unroll
            for (int nt = 0; nt < 8; ++nt) {
                const unsigned b0 = bh[nt >> 1][(nt & 1) * 2];
                const unsigned b1 = bh[nt >> 1][(nt & 1) * 2 + 1];
                const unsigned c0 = bl[nt >> 1][(nt & 1) * 2];
                const unsigned c1 = bl[nt >> 1][(nt & 1) * 2 + 1];
                float* d = acc[mt][nt];
                mma_bf16(d, ah[0], ah[1], ah[2], ah[3], b0, b1); // hh
                mma_bf16(d, al[0], al[1], al[2], al[3], b0, b1); // lh
                mma_bf16(d, ah[0], ah[1], ah[2], ah[3], c0, c1); // hl
            }
        }

        if (more) {
            const int nxt = cur ^ 1;
            unsigned* sb = &sm[nxt * BUFW];
            *reinterpret_cast<uint4*>(&sb[0 * APLANE + sa])     = fa0;
            *reinterpret_cast<uint4*>(&sb[0 * APLANE + sa + 4]) = fa1;
            *reinterpret_cast<uint4*>(&sb[1 * APLANE + sa])     = fl0;
            *reinterpret_cast<uint4*>(&sb[1 * APLANE + sa + 4]) = fl1;
            *reinterpret_cast<uint4*>(&sb[2 * APLANE + swr])          = fwh;
            *reinterpret_cast<uint4*>(&sb[2 * APLANE + WPLANE + swr]) = fwl;
        }
        __syncthreads();
    }

    if (epi == 3) {
        // k-projection: per-row norm over each 32-col head band.
        // Warp band = 64 cols = 2 heads: nt 0..3 -> head 0, nt 4..7 -> head 1.
#pragma unroll
        for (int mt = 0; mt < 4; ++mt) {
            float sE[2] = {0.f, 0.f}, sO[2] = {0.f, 0.f};
#pragma unroll
            for (int nt = 0; nt < 8; ++nt) {
                const int hsel = nt >> 2;
                sE[hsel] = fmaf(acc[mt][nt][0], acc[mt][nt][0], sE[hsel]);
                sE[hsel] = fmaf(acc[mt][nt][1], acc[mt][nt][1], sE[hsel]);
                sO[hsel] = fmaf(acc[mt][nt][2], acc[mt][nt][2], sO[hsel]);
                sO[hsel] = fmaf(acc[mt][nt][3], acc[mt][nt][3], sO[hsel]);
            }
            float iE[2], iO[2];
#pragma unroll
            for (int h2 = 0; h2 < 2; ++h2) {
                float se = sE[h2], so = sO[h2];
                se += __shfl_xor_sync(0xffffffffu, se, 1);
                se += __shfl_xor_sync(0xffffffffu, se, 2);
                so += __shfl_xor_sync(0xffffffffu, so, 1);
                so += __shfl_xor_sync(0xffffffffu, so, 2);
                iE[h2] = __fdividef(1.f, sqrtf(se) + 1e-6f);
                iO[h2] = __fdividef(1.f, sqrtf(so) + 1e-6f);
            }
            const int r0 = row0 + wm + mt * 16 + g;
#pragma unroll
            for (int nt = 0; nt < 8; ++nt) {
                const int hsel = nt >> 2;
                const int cc = col0 + wn + nt * 8 + 2 * c;
                *reinterpret_cast<float2*>(C + (size_t)r0 * Nout + cc) =
                    make_float2(acc[mt][nt][0] * iE[hsel], acc[mt][nt][1] * iE[hsel]);
                *reinterpret_cast<float2*>(C + (size_t)(r0 + 8) * Nout + cc) =
                    make_float2(acc[mt][nt][2] * iO[hsel], acc[mt][nt][3] * iO[hsel]);
            }
        }
        return;
    }

#pragma unroll
    for (int mt = 0; mt < 4; ++mt) {
        const int r0 = row0 + wm + mt * 16 + g;
#pragma unroll
        for (int nt = 0; nt < 8; ++nt) {
            const int cc = col0 + wn + nt * 8 + 2 * c;
            float d0 = acc[mt][nt][0], d1 = acc[mt][nt][1];
            float d2 = acc[mt][nt][2], d3 = acc[mt][nt][3];
            if (epi == 4) {
                d0 = d0 * __fdividef(1.f, 1.f + __expf(-d0));
                d1 = d1 * __fdividef(1.f, 1.f + __expf(-d1));
                d2 = d2 * __fdividef(1.f, 1.f + __expf(-d2));
                d3 = d3 * __fdividef(1.f, 1.f + __expf(-d3));
                const size_t w0 = ((size_t)r0 * Nout + cc) >> 1;
                const size_t w1 = ((size_t)(r0 + 8) * Nout + cc) >> 1;
                Chi[w0] = pack_hi_pair(d0, d1);
                Clo[w0] = pack_lo_pair(d0 - trunc_hi(d0), d1 - trunc_hi(d1));
                Chi[w1] = pack_hi_pair(d2, d3);
                Clo[w1] = pack_lo_pair(d2 - trunc_hi(d2), d3 - trunc_hi(d3));
                continue;
            }
            if (epi == 2) {
                const float b0 = bias[cc], b1 = bias[cc + 1];
                d0 = __fdividef(1.f, 1.f + __expf(-(d0 + b0)));
                d1 = __fdividef(1.f, 1.f + __expf(-(d1 + b1)));
                d2 = __fdividef(1.f, 1.f + __expf(-(d2 + b0)));
                d3 = __fdividef(1.f, 1.f + __expf(-(d3 + b1)));
            }
            *reinterpret_cast<float2*>(C + (size_t)r0 * Nout + cc)       = make_float2(d0, d1);
            *reinterpret_cast<float2*>(C + (size_t)(r0 + 8) * Nout + cc) = make_float2(d2, d3);
        }
    }
}

template<int EPI>
__global__ void __launch_bounds__(256, 1)
gemm_bf16(const unsigned* __restrict__ Ah, const unsigned* __restrict__ Al,
          const unsigned* __restrict__ Wh, const unsigned* __restrict__ Wl,
          float* __restrict__ C, unsigned* __restrict__ Chi, unsigned* __restrict__ Clo,
          const float* __restrict__ bias, int Nout, int Kw)
{
    mma_gemm_core(Ah, Al, Wh, Wl, C, Chi, Clo, bias, EPI, Nout, Kw,
                  blockIdx.y * 256, blockIdx.x * 128);
}

struct ProjPtrs {
    const unsigned* Wh[4];
    const unsigned* Wl[4];
    float*          C[4];
};

// z: 0 = k (head-band normalize), 1 = v, 2 = q, 3 = beta (sigmoid+bias)
__global__ void __launch_bounds__(256, 1)
gemm_proj4(const unsigned* __restrict__ Ah, const unsigned* __restrict__ Al,
           ProjPtrs p, const float* __restrict__ bias, int Nout, int Kw)
{
    const int z = blockIdx.z;
    const int epi = (z == 0) ? 3 : ((z == 3) ? 2 : 0);
    mma_gemm_core(Ah, Al, p.Wh[z], p.Wl[z], p.C[z], nullptr, nullptr, bias,
                  epi, Nout, Kw, blockIdx.y * 256, blockIdx.x * 128);
}

// ---------------------------------------------------------------------------
// Barrier-free sequential scan (proven round-8/9 tiling: 2 cols/lane,
// 2 rows/warp, 16 warps/chain). Writes cell as split bf16 hi/lo planes.
// ---------------------------------------------------------------------------
#define PF 4

__global__ void __launch_bounds__(128)
scan_kernel(const float* __restrict__ Kn, const float* __restrict__ Vp,
            const float* __restrict__ Qp, const float* __restrict__ Bp,
            unsigned short* __restrict__ cellh, unsigned short* __restrict__ celll,
            float* __restrict__ S_final, int writeS)
{
    const int g     = blockIdx.x * 4 + (threadIdx.x >> 5);
    const int chain = g >> 4;
    const int wc    = g & 15;
    const int l     = threadIdx.x & 31;
    const int i     = wc * 2 + (l >> 4);
    const int j0    = (l & 15) * 2;
    const size_t cb = ((size_t)(chain >> 3) * TT) * HN + (size_t)(chain & 7) * NN;

    float2 pk[PF], pq[PF];
    float  pv[PF], pb[PF];
#pragma unroll
    for (int d = 0; d < PF; ++d) {
        const size_t a = cb + (size_t)d * HN;
        pk[d] = *reinterpret_cast<const float2*>(Kn + a + j0);
        pq[d] = *reinterpret_cast<const float2*>(Qp + a + j0);
        pv[d] = Vp[a + i];
        pb[d] = Bp[a + i];
    }

    float S0 = 0.f, S1 = 0.f, sqp = 0.f;
    size_t base = cb;

    for (int t = 0; t < TT; t += PF) {
#pragma unroll
        for (int u = 0; u < PF; ++u) {
            const int tcur = t + u;
            const int tpre = (tcur + PF < TT) ? (tcur + PF) : (TT - 1);
            const size_t pa = cb + (size_t)tpre * HN;
            const float2 nk = *reinterpret_cast<const float2*>(Kn + pa + j0);
            const float2 nq = *reinterpret_cast<const float2*>(Qp + pa + j0);
            const float  nv = Vp[pa + i];
            const float  nb = Bp[pa + i];

            const float k0 = pk[u].x, k1 = pk[u].y;

            float uu = fmaf(S1, k1, S0 * k0);
            float sv = sqp;
#pragma unroll
            for (int o = 1; o < 16; o <<= 1) {
                uu += __shfl_xor_sync(0xffffffffu, uu, o);
                sv += __shfl_xor_sync(0xffffffffu, sv, o);
            }
            if (tcur > 0 && (l & 15) == 0) {
                const float ov = sv * sv * __fdividef(1.f, 1.f + __expf(-sv));
                cellh[base - HN + i] = (unsigned short)(__float_as_uint(ov) >> 16);
                unsigned short lo16;
                const float res = ov - trunc_hi(ov);
                asm("cvt.rn.bf16.f32 %0, %1;" : "=h"(lo16) : "f"(res));
                celll[base - HN + i] = lo16;
            }

            const float delta = pv[u] - uu;
            const float bi    = pb[u];
            const float z0 = fmaf(bi, S0, delta * k0);
            const float z1 = fmaf(bi, S1, delta * k1);
            const float e0 = __expf(2.f * z0);
            const float e1 = __expf(2.f * z1);
            S0 = 1.f - __fdividef(2.f, e0 + 1.f);
            S1 = 1.f - __fdividef(2.f, e1 + 1.f);

            sqp = fmaf(S1, pq[u].y, S0 * pq[u].x);

            pk[u] = nk; pq[u] = nq; pv[u] = nv; pb[u] = nb;
            base += HN;
        }
    }

    float sv = sqp;
#pragma unroll
    for (int o = 1; o < 16; o <<= 1) sv += __shfl_xor_sync(0xffffffffu, sv, o);
    if ((l & 15) == 0) {
        const float ov = sv * sv * __fdividef(1.f, 1.f + __expf(-sv));
        cellh[base - HN + i] = (unsigned short)(__float_as_uint(ov) >> 16);
        unsigned short lo16;
        const float res = ov - trunc_hi(ov);
        asm("cvt.rn.bf16.f32 %0, %1;" : "=h"(lo16) : "f"(res));
        celll[base - HN + i] = lo16;
    }

    if (writeS) {
        S_final[((size_t)chain * NN + i) * NN + j0]     = S0;
        S_final[((size_t)chain * NN + i) * NN + j0 + 1] = S1;
    }
}

// ---------------------------------------------------------------------------
// Host launcher
// ---------------------------------------------------------------------------
extern "C" void kernel_launch(void* const* d_in, const int* in_sizes, int n_in,
                              void* d_out, int out_size)
{
    const float* x      = (const float*)d_in[0];
    const float* W_in   = (const float*)d_in[1];
    const float* W_k    = (const float*)d_in[2];
    const float* W_v    = (const float*)d_in[3];
    const float* W_q    = (const float*)d_in[4];
    const float* W_beta = (const float*)d_in[5];
    const float* b_beta = (const float*)d_in[6];
    const float* W_out  = (const float*)d_in[7];
    float* y = (float*)d_out;

    unsigned *xh, *xl, *xph, *xpl, *wih, *wil;
    unsigned *wkh, *wkl, *wvh, *wvl, *wqh, *wql, *wbh, *wbl, *woh, *wol;
    float *k, *v, *q, *bt;
    unsigned short *cellh, *celll;
    cudaGetSymbolAddress((void**)&xh,  g_xh);  cudaGetSymbolAddress((void**)&xl,  g_xl);
    cudaGetSymbolAddress((void**)&xph, g_xph); cudaGetSymbolAddress((void**)&xpl, g_xpl);
    cudaGetSymbolAddress((void**)&wih, g_wih); cudaGetSymbolAddress((void**)&wil, g_wil);
    cudaGetSymbolAddress((void**)&wkh, g_wkh); cudaGetSymbolAddress((void**)&wkl, g_wkl);
    cudaGetSymbolAddress((void**)&wvh, g_wvh); cudaGetSymbolAddress((void**)&wvl, g_wvl);
    cudaGetSymbolAddress((void**)&wqh, g_wqh); cudaGetSymbolAddress((void**)&wql, g_wql);
    cudaGetSymbolAddress((void**)&wbh, g_wbh); cudaGetSymbolAddress((void**)&wbl, g_wbl);
    cudaGetSymbolAddress((void**)&woh, g_woh); cudaGetSymbolAddress((void**)&wol, g_wol);
    cudaGetSymbolAddress((void**)&k,  g_k);  cudaGetSymbolAddress((void**)&v,  g_v);
    cudaGetSymbolAddress((void**)&q,  g_q);  cudaGetSymbolAddress((void**)&bt, g_beta);
    cudaGetSymbolAddress((void**)&cellh, g_cellh);
    cudaGetSymbolAddress((void**)&celll, g_celll);

    cudaFuncSetAttribute(gemm_bf16<0>, cudaFuncAttributeMaxDynamicSharedMemorySize, SMEM_GB);
    cudaFuncSetAttribute(gemm_bf16<4>, cudaFuncAttributeMaxDynamicSharedMemorySize, SMEM_GB);
    cudaFuncSetAttribute(gemm_proj4,   cudaFuncAttributeMaxDynamicSharedMemorySize, SMEM_GB);

    const int M = MROWS;

    // 0. split fp32 operands into bf16 hi/lo planes
    split_kernel<<<(M * DD / 2) / 256, 256>>>((const float2*)x, xh, xl, M * DD / 2);
    split_kernel<<<(DD * DD / 2) / 256, 256>>>((const float2*)W_in, wih, wil, DD * DD / 2);
    split_kernel<<<(HN * DD / 2) / 256, 256>>>((const float2*)W_k, wkh, wkl, HN * DD / 2);
    split_kernel<<<(HN * DD / 2) / 256, 256>>>((const float2*)W_v, wvh, wvl, HN * DD / 2);
    split_kernel<<<(HN * DD / 2) / 256, 256>>>((const float2*)W_q, wqh, wql, HN * DD / 2);
    split_kernel<<<(HN * DD / 2) / 256, 256>>>((const float2*)W_beta, wbh, wbl, HN * DD / 2);
    split_kernel<<<(DD * HN / 2) / 256, 256>>>((const float2*)W_out, woh, wol, DD * HN / 2);

    // 1. xp = silu(x @ W_in^T) -> split planes (epi 4)
    gemm_bf16<4><<<dim3(DD / 128, M / 256), 256, SMEM_GB>>>(
        xh, xl, wih, wil, nullptr, xph, xpl, nullptr, DD, DD / 2);

    // 2. fused projections: k (normalized), v, q, beta
    ProjPtrs p;
    p.Wh[0] = wkh; p.Wl[0] = wkl; p.C[0] = k;
    p.Wh[1] = wvh; p.Wl[1] = wvl; p.C[1] = v;
    p.Wh[2] = wqh; p.Wl[2] = wql; p.C[2] = q;
    p.Wh[3] = wbh; p.Wl[3] = wbl; p.C[3] = bt;
    gemm_proj4<<<dim3(HN / 128, M / 256, 4), 256, SMEM_GB>>>(
        xph, xpl, p, b_beta, HN, DD / 2);

    // 3. sequential scan (writes cell as split bf16 planes)
    const size_t y_elems = (size_t)M * DD;
    const int writeS = (out_size >= (int)(y_elems + (size_t)BB * HH * NN * NN)) ? 1 : 0;
    scan_kernel<<<256, 128>>>(k, v, q, bt, cellh, celll, y + y_elems, writeS);

    // 4. y = cell @ W_out^T
    gemm_bf16<0><<<dim3(DD / 128, M / 256), 256, SMEM_GB>>>(
        (const unsigned*)cellh, (const unsigned*)celll, woh, wol,
        y, nullptr, nullptr, nullptr, DD, HN / 2);
}

// round 12
// speedup vs baseline: 1.0004x; 1.0004x over previous
#include <cuda_runtime.h>
#include <cstddef>
#include <cstdint>

// Problem constants
#define BB 8
#define TT 2048
#define DD 1024
#define HH 8
#define NN 32
#define MROWS (BB*TT)          // 16384
#define HN (HH*NN)             // 256

// ---------------------------------------------------------------------------
// Scratch (no cudaMalloc allowed) — __device__ globals.
// Split planes: packed bf16 pairs (one u32 = 2 bf16 along K).
// ---------------------------------------------------------------------------
__device__ unsigned g_xh [(size_t)MROWS * DD / 2];
__device__ unsigned g_xl [(size_t)MROWS * DD / 2];
__device__ unsigned g_xph[(size_t)MROWS * DD / 2];
__device__ unsigned g_xpl[(size_t)MROWS * DD / 2];
__device__ unsigned g_wih[(size_t)DD * DD / 2];
__device__ unsigned g_wil[(size_t)DD * DD / 2];
__device__ unsigned g_wkh[(size_t)HN * DD / 2];
__device__ unsigned g_wkl[(size_t)HN * DD / 2];
__device__ unsigned g_wvh[(size_t)HN * DD / 2];
__device__ unsigned g_wvl[(size_t)HN * DD / 2];
__device__ unsigned g_wqh[(size_t)HN * DD / 2];
__device__ unsigned g_wql[(size_t)HN * DD / 2];
__device__ unsigned g_wbh[(size_t)HN * DD / 2];
__device__ unsigned g_wbl[(size_t)HN * DD / 2];
__device__ unsigned g_woh[(size_t)DD * HN / 2];
__device__ unsigned g_wol[(size_t)DD * HN / 2];
__device__ float    g_k   [(size_t)MROWS * HN];
__device__ float    g_v   [(size_t)MROWS * HN];
__device__ float    g_q   [(size_t)MROWS * HN];
__device__ float    g_beta[(size_t)MROWS * HN];
__device__ unsigned short g_cellh[(size_t)MROWS * HN];
__device__ unsigned short g_celll[(size_t)MROWS * HN];

// ---------------------------------------------------------------------------
// bf16 split helpers
// ---------------------------------------------------------------------------
__device__ __forceinline__ float trunc_hi(float x) {
    return __uint_as_float(__float_as_uint(x) & 0xFFFF0000u);
}
__device__ __forceinline__ unsigned pack_hi_pair(float e0, float e1) {
    return __byte_perm(__float_as_uint(e0), __float_as_uint(e1), 0x7632);
}
__device__ __forceinline__ unsigned pack_lo_pair(float l0, float l1) {
    unsigned d;
    asm("cvt.rn.bf16x2.f32 %0, %1, %2;" : "=r"(d) : "f"(l1), "f"(l0));
    return d;
}

__global__ void __launch_bounds__(256)
split_kernel(const float2* __restrict__ in, unsigned* __restrict__ hi,
             unsigned* __restrict__ lo, int n)
{
    const int i = blockIdx.x * 256 + threadIdx.x;
    if (i < n) {
        const float2 v = in[i];
        hi[i] = pack_hi_pair(v.x, v.y);
        lo[i] = pack_lo_pair(v.x - trunc_hi(v.x), v.y - trunc_hi(v.y));
    }
}

__device__ __forceinline__ void mma_bf16(float d[4],
                                         unsigned a0, unsigned a1,
                                         unsigned a2, unsigned a3,
                                         unsigned b0, unsigned b1) {
    asm("mma.sync.aligned.m16n8k16.row.col.f32.bf16.bf16.f32 "
        "{%0,%1,%2,%3}, {%4,%5,%6,%7}, {%8,%9}, {%0,%1,%2,%3};"
        : "+f"(d[0]), "+f"(d[1]), "+f"(d[2]), "+f"(d[3])
        : "r"(a0), "r"(a1), "r"(a2), "r"(a3), "r"(b0), "r"(b1));
}

__device__ __forceinline__ void ldsm4(unsigned& r0, unsigned& r1,
                                      unsigned& r2, unsigned& r3, unsigned addr) {
    asm volatile("ldmatrix.sync.aligned.m8n8.x4.shared.b16 {%0,%1,%2,%3}, [%4];"
                 : "=r"(r0), "=r"(r1), "=r"(r2), "=r"(r3) : "r"(addr));
}

// ---------------------------------------------------------------------------
// bf16x2-compensated tensor GEMM on pre-split operands.
// C = epi( A @ W^T ). Block tile 256(M) x 128(N), chunk k16 (8 u32 words),
// 8 warps as 4M x 2N -> warp tile 64x64. Per chunk per warp:
// 16 ldmatrix.x4 + 96 HMMA  (1.5x more HMMA per LDS byte than 64x32).
// epi: 0 identity(f32), 2 sigmoid(acc+bias), 3 head-band row-norm,
//      4 silu + split-write
// ---------------------------------------------------------------------------
#define PLW 12
#define APLANE (256 * PLW)          // u32 per A plane
#define WPLANE (128 * PLW)          // u32 per W plane
#define BUFW (2 * APLANE + 2 * WPLANE)   // u32 per stage buffer (9216)
#define SMEM_GB (2 * BUFW * 4)           // 73728 bytes

__device__ __forceinline__ void mma_gemm_core(
    const unsigned* __restrict__ Ah, const unsigned* __restrict__ Al,
    const unsigned* __restrict__ Wh, const unsigned* __restrict__ Wl,
    float* __restrict__ C, unsigned* __restrict__ Chi, unsigned* __restrict__ Clo,
    const float* __restrict__ bias,
    int epi, int Nout, int Kw, int row0, int col0)
{
    extern __shared__ unsigned sm[];   // [2][BUFW]

    const int tid  = threadIdx.x;
    const int wid  = tid >> 5;
    const int lane = tid & 31;
    const int g    = lane >> 2;
    const int c    = lane & 3;
    const int wm   = (wid & 3) * 64;   // warp M offset (0..192)
    const int wn   = (wid >> 2) * 64;  // warp N offset (0 or 64)

    // staging: A row = tid (8 words), W row = tid>>1 (4 words, half = tid&1)
    const unsigned* ApH = Ah + (size_t)(row0 + tid) * Kw;
    const unsigned* ApL = Al + (size_t)(row0 + tid) * Kw;
    const int wrow = tid >> 1;
    const int whalf = (tid & 1) * 4;
    const unsigned* WpH = Wh + (size_t)(col0 + wrow) * Kw + whalf;
    const unsigned* WpL = Wl + (size_t)(col0 + wrow) * Kw + whalf;
    const int sa = tid * PLW;              // A smem row base (u32)
    const int swr = wrow * PLW + whalf;    // W smem row base (u32)

    const unsigned smb = (unsigned)__cvta_generic_to_shared(&sm[0]);
    const unsigned aoff = (((lane & 15) * PLW) + ((lane >> 4) << 2)) * 4;
    const unsigned boff = ((((lane >> 4) * 8 + (lane & 7)) * PLW) + ((lane & 8) ? 4 : 0)) * 4;

    float acc[4][8][4];
#pragma unroll
    for (int mt = 0; mt < 4; ++mt)
#pragma unroll
        for (int nt = 0; nt < 8; ++nt)
#pragma unroll
            for (int e = 0; e < 4; ++e) acc[mt][nt][e] = 0.f;

    const int nchunks = Kw / 8;

    // prologue: stage chunk 0 into buffer 0
    {
        *reinterpret_cast<uint4*>(&sm[0 * APLANE + sa])     = *reinterpret_cast<const uint4*>(ApH);
        *reinterpret_cast<uint4*>(&sm[0 * APLANE + sa + 4]) = *reinterpret_cast<const uint4*>(ApH + 4);
        *reinterpret_cast<uint4*>(&sm[1 * APLANE + sa])     = *reinterpret_cast<const uint4*>(ApL);
        *reinterpret_cast<uint4*>(&sm[1 * APLANE + sa + 4]) = *reinterpret_cast<const uint4*>(ApL + 4);
        *reinterpret_cast<uint4*>(&sm[2 * APLANE + swr])          = *reinterpret_cast<const uint4*>(WpH);
        *reinterpret_cast<uint4*>(&sm[2 * APLANE + WPLANE + swr]) = *reinterpret_cast<const uint4*>(WpL);
    }
    __syncthreads();

    for (int chunk = 0; chunk < nchunks; ++chunk) {
        const int cur = chunk & 1;
        const bool more = (chunk + 1 < nchunks);

        uint4 fa0, fa1, fl0, fl1, fwh, fwl;
        if (more) {
            const int ko = (chunk + 1) * 8;
            fa0 = *reinterpret_cast<const uint4*>(ApH + ko);
            fa1 = *reinterpret_cast<const uint4*>(ApH + ko + 4);
            fl0 = *reinterpret_cast<const uint4*>(ApL + ko);
            fl1 = *reinterpret_cast<const uint4*>(ApL + ko + 4);
            fwh = *reinterpret_cast<const uint4*>(WpH + ko);
            fwl = *reinterpret_cast<const uint4*>(WpL + ko);
        }

        const unsigned pb = smb + (unsigned)cur * (BUFW * 4);

        // B fragments: 4 nt-pairs x (hi, lo)  (warp N band = 64 cols)
        unsigned bh[4][4], bl[4][4];
#pragma unroll
        for (int pr = 0; pr < 4; ++pr) {
            const unsigned ba = pb + (2 * APLANE) * 4 + (unsigned)(wn + pr * 16) * PLW * 4 + boff;
            ldsm4(bh[pr][0], bh[pr][1], bh[pr][2], bh[pr][3], ba);
            ldsm4(bl[pr][0], bl[pr][1], bl[pr][2], bl[pr][3], ba + WPLANE * 4);
        }

#pragma unroll
        for (int mt = 0; mt < 4; ++mt) {
            unsigned ah[4], al[4];
            const unsigned aa = pb + (unsigned)(wm + mt * 16) * PLW * 4 + aoff;
            ldsm4(ah[0], ah[1], ah[2], ah[3], aa);
            ldsm4(al[0], al[1], al[2], al[3], aa + APLANE * 4);
#pragma unroll
            for (int nt = 0; nt < 8; ++nt) {
                const unsigned b0 = bh[nt >> 1][(nt & 1) * 2];
                const unsigned b1 = bh[nt >> 1][(nt & 1) * 2 + 1];
                const unsigned c0 = bl[nt >> 1][(nt & 1) * 2];
                const unsigned c1 = bl[nt >> 1][(nt & 1) * 2 + 1];
                float* d = acc[mt][nt];
                mma_bf16(d, ah[0], ah[1], ah[2], ah[3], b0, b1); // hh
                mma_bf16(d, al[0], al[1], al[2], al[3], b0, b1); // lh
                mma_bf16(d, ah[0], ah[1], ah[2], ah[3], c0, c1); // hl
            }
        }

        if (more) {
            const int nxt = cur ^ 1;
            unsigned* sb = &sm[nxt * BUFW];
            *reinterpret_cast<uint4*>(&sb[0 * APLANE + sa])     = fa0;
            *reinterpret_cast<uint4*>(&sb[0 * APLANE + sa + 4]) = fa1;
            *reinterpret_cast<uint4*>(&sb[1 * APLANE + sa])     = fl0;
            *reinterpret_cast<uint4*>(&sb[1 * APLANE + sa + 4]) = fl1;
            *reinterpret_cast<uint4*>(&sb[2 * APLANE + swr])          = fwh;
            *reinterpret_cast<uint4*>(&sb[2 * APLANE + WPLANE + swr]) = fwl;
        }
        __syncthreads();
    }

    if (epi == 3) {
        // k-projection: per-row norm over each 32-col head band.
        // Warp band = 64 cols = 2 heads: nt 0..3 -> head 0, nt 4..7 -> head 1.
#pragma unroll
        for (int mt = 0; mt < 4; ++mt) {
            float sE[2] = {0.f, 0.f}, sO[2] = {0.f, 0.f};
#pragma unroll
            for (int nt = 0; nt < 8; ++nt) {
                const int hsel = nt >> 2;
                sE[hsel] = fmaf(acc[mt][nt][0], acc[mt][nt][0], sE[hsel]);
                sE[hsel] = fmaf(acc[mt][nt][1], acc[mt][nt][1], sE[hsel]);
                sO[hsel] = fmaf(acc[mt][nt][2], acc[mt][nt][2], sO[hsel]);
                sO[hsel] = fmaf(acc[mt][nt][3], acc[mt][nt][3], sO[hsel]);
            }
            float iE[2], iO[2];
#pragma unroll
            for (int h2 = 0; h2 < 2; ++h2) {
                float se = sE[h2], so = sO[h2];
                se += __shfl_xor_sync(0xffffffffu, se, 1);
                se += __shfl_xor_sync(0xffffffffu, se, 2);
                so += __shfl_xor_sync(0xffffffffu, so, 1);
                so += __shfl_xor_sync(0xffffffffu, so, 2);
                iE[h2] = __fdividef(1.f, sqrtf(se) + 1e-6f);
                iO[h2] = __fdividef(1.f, sqrtf(so) + 1e-6f);
            }
            const int r0 = row0 + wm + mt * 16 + g;
#pragma unroll
            for (int nt = 0; nt < 8; ++nt) {
                const int hsel = nt >> 2;
                const int cc = col0 + wn + nt * 8 + 2 * c;
                *reinterpret_cast<float2*>(C + (size_t)r0 * Nout + cc) =
                    make_float2(acc[mt][nt][0] * iE[hsel], acc[mt][nt][1] * iE[hsel]);
                *reinterpret_cast<float2*>(C + (size_t)(r0 + 8) * Nout + cc) =
                    make_float2(acc[mt][nt][2] * iO[hsel], acc[mt][nt][3] * iO[hsel]);
            }
        }
        return;
    }

#pragma unroll
    for (int mt = 0; mt < 4; ++mt) {
        const int r0 = row0 + wm + mt * 16 + g;
#pragma unroll
        for (int nt = 0; nt < 8; ++nt) {
            const int cc = col0 + wn + nt * 8 + 2 * c;
            float d0 = acc[mt][nt][0], d1 = acc[mt][nt][1];
            float d2 = acc[mt][nt][2], d3 = acc[mt][nt][3];
            if (epi == 4) {
                d0 = d0 * __fdividef(1.f, 1.f + __expf(-d0));
                d1 = d1 * __fdividef(1.f, 1.f + __expf(-d1));
                d2 = d2 * __fdividef(1.f, 1.f + __expf(-d2));
                d3 = d3 * __fdividef(1.f, 1.f + __expf(-d3));
                const size_t w0 = ((size_t)r0 * Nout + cc) >> 1;
                const size_t w1 = ((size_t)(r0 + 8) * Nout + cc) >> 1;
                Chi[w0] = pack_hi_pair(d0, d1);
                Clo[w0] = pack_lo_pair(d0 - trunc_hi(d0), d1 - trunc_hi(d1));
                Chi[w1] = pack_hi_pair(d2, d3);
                Clo[w1] = pack_lo_pair(d2 - trunc_hi(d2), d3 - trunc_hi(d3));
                continue;
            }
            if (epi == 2) {
                const float b0 = bias[cc], b1 = bias[cc + 1];
                d0 = __fdividef(1.f, 1.f + __expf(-(d0 + b0)));
                d1 = __fdividef(1.f, 1.f + __expf(-(d1 + b1)));
                d2 = __fdividef(1.f, 1.f + __expf(-(d2 + b0)));
                d3 = __fdividef(1.f, 1.f + __expf(-(d3 + b1)));
            }
            *reinterpret_cast<float2*>(C + (size_t)r0 * Nout + cc)       = make_float2(d0, d1);
            *reinterpret_cast<float2*>(C + (size_t)(r0 + 8) * Nout + cc) = make_float2(d2, d3);
        }
    }
}

template<int EPI>
__global__ void __launch_bounds__(256, 1)
gemm_bf16(const unsigned* __restrict__ Ah, const unsigned* __restrict__ Al,
          const unsigned* __restrict__ Wh, const unsigned* __restrict__ Wl,
          float* __restrict__ C, unsigned* __restrict__ Chi, unsigned* __restrict__ Clo,
          const float* __restrict__ bias, int Nout, int Kw)
{
    mma_gemm_core(Ah, Al, Wh, Wl, C, Chi, Clo, bias, EPI, Nout, Kw,
                  blockIdx.y * 256, blockIdx.x * 128);
}

struct ProjPtrs {
    const unsigned* Wh[4];
    const unsigned* Wl[4];
    float*          C[4];
};

// z: 0 = k (head-band normalize), 1 = v, 2 = q, 3 = beta (sigmoid+bias)
__global__ void __launch_bounds__(256, 1)
gemm_proj4(const unsigned* __restrict__ Ah, const unsigned* __restrict__ Al,
           ProjPtrs p, const float* __restrict__ bias, int Nout, int Kw)
{
    const int z = blockIdx.z;
    const int epi = (z == 0) ? 3 : ((z == 3) ? 2 : 0);
    mma_gemm_core(Ah, Al, p.Wh[z], p.Wl[z], p.C[z], nullptr, nullptr, bias,
                  epi, Nout, Kw, blockIdx.y * 256, blockIdx.x * 128);
}

// ---------------------------------------------------------------------------
// Barrier-free sequential scan (proven round-8/9 tiling: 2 cols/lane,
// 2 rows/warp, 16 warps/chain). Writes cell as split bf16 hi/lo planes.
// ---------------------------------------------------------------------------
#define PF 4

__global__ void __launch_bounds__(128)
scan_kernel(const float* __restrict__ Kn, const float* __restrict__ Vp,
            const float* __restrict__ Qp, const float* __restrict__ Bp,
            unsigned short* __restrict__ cellh, unsigned short* __restrict__ celll,
            float* __restrict__ S_final, int writeS)
{
    const int g     = blockIdx.x * 4 + (threadIdx.x >> 5);
    const int chain = g >> 4;
    const int wc    = g & 15;
    const int l     = threadIdx.x & 31;
    const int i     = wc * 2 + (l >> 4);
    const int j0    = (l & 15) * 2;
    const size_t cb = ((size_t)(chain >> 3) * TT) * HN + (size_t)(chain & 7) * NN;

    float2 pk[PF], pq[PF];
    float  pv[PF], pb[PF];
#pragma unroll
    for (int d = 0; d < PF; ++d) {
        const size_t a = cb + (size_t)d * HN;
        pk[d] = *reinterpret_cast<const float2*>(Kn + a + j0);
        pq[d] = *reinterpret_cast<const float2*>(Qp + a + j0);
        pv[d] = Vp[a + i];
        pb[d] = Bp[a + i];
    }

    float S0 = 0.f, S1 = 0.f, sqp = 0.f;
    size_t base = cb;

    for (int t = 0; t < TT; t += PF) {
#pragma unroll
        for (int u = 0; u < PF; ++u) {
            const int tcur = t + u;
            const int tpre = (tcur + PF < TT) ? (tcur + PF) : (TT - 1);
            const size_t pa = cb + (size_t)tpre * HN;
            const float2 nk = *reinterpret_cast<const float2*>(Kn + pa + j0);
            const float2 nq = *reinterpret_cast<const float2*>(Qp + pa + j0);
            const float  nv = Vp[pa + i];
            const float  nb = Bp[pa + i];

            const float k0 = pk[u].x, k1 = pk[u].y;

            float uu = fmaf(S1, k1, S0 * k0);
            float sv = sqp;
#pragma unroll
            for (int o = 1; o < 16; o <<= 1) {
                uu += __shfl_xor_sync(0xffffffffu, uu, o);
                sv += __shfl_xor_sync(0xffffffffu, sv, o);
            }
            if (tcur > 0 && (l & 15) == 0) {
                const float ov = sv * sv * __fdividef(1.f, 1.f + __expf(-sv));
                cellh[base - HN + i] = (unsigned short)(__float_as_uint(ov) >> 16);
                unsigned short lo16;
                const float res = ov - trunc_hi(ov);
                asm("cvt.rn.bf16.f32 %0, %1;" : "=h"(lo16) : "f"(res));
                celll[base - HN + i] = lo16;
            }

            const float delta = pv[u] - uu;
            const float bi    = pb[u];
            const float z0 = fmaf(bi, S0, delta * k0);
            const float z1 = fmaf(bi, S1, delta * k1);
            const float e0 = __expf(2.f * z0);
            const float e1 = __expf(2.f * z1);
            S0 = 1.f - __fdividef(2.f, e0 + 1.f);
            S1 = 1.f - __fdividef(2.f, e1 + 1.f);

            sqp = fmaf(S1, pq[u].y, S0 * pq[u].x);

            pk[u] = nk; pq[u] = nq; pv[u] = nv; pb[u] = nb;
            base += HN;
        }
    }

    float sv = sqp;
#pragma unroll
    for (int o = 1; o < 16; o <<= 1) sv += __shfl_xor_sync(0xffffffffu, sv, o);
    if ((l & 15) == 0) {
        const float ov = sv * sv * __fdividef(1.f, 1.f + __expf(-sv));
        cellh[base - HN + i] = (unsigned short)(__float_as_uint(ov) >> 16);
        unsigned short lo16;
        const float res = ov - trunc_hi(ov);
        asm("cvt.rn.bf16.f32 %0, %1;" : "=h"(lo16) : "f"(res));
        celll[base - HN + i] = lo16;
    }

    if (writeS) {
        S_final[((size_t)chain * NN + i) * NN + j0]     = S0;
        S_final[((size_t)chain * NN + i) * NN + j0 + 1] = S1;
    }
}

// ---------------------------------------------------------------------------
// Host launcher
// ---------------------------------------------------------------------------
extern "C" void kernel_launch(void* const* d_in, const int* in_sizes, int n_in,
                              void* d_out, int out_size)
{
    const float* x      = (const float*)d_in[0];
    const float* W_in   = (const float*)d_in[1];
    const float* W_k    = (const float*)d_in[2];
    const float* W_v    = (const float*)d_in[3];
    const float* W_q    = (const float*)d_in[4];
    const float* W_beta = (const float*)d_in[5];
    const float* b_beta = (const float*)d_in[6];
    const float* W_out  = (const float*)d_in[7];
    float* y = (float*)d_out;

    unsigned *xh, *xl, *xph, *xpl, *wih, *wil;
    unsigned *wkh, *wkl, *wvh, *wvl, *wqh, *wql, *wbh, *wbl, *woh, *wol;
    float *k, *v, *q, *bt;
    unsigned short *cellh, *celll;
    cudaGetSymbolAddress((void**)&xh,  g_xh);  cudaGetSymbolAddress((void**)&xl,  g_xl);
    cudaGetSymbolAddress((void**)&xph, g_xph); cudaGetSymbolAddress((void**)&xpl, g_xpl);
    cudaGetSymbolAddress((void**)&wih, g_wih); cudaGetSymbolAddress((void**)&wil, g_wil);
    cudaGetSymbolAddress((void**)&wkh, g_wkh); cudaGetSymbolAddress((void**)&wkl, g_wkl);
    cudaGetSymbolAddress((void**)&wvh, g_wvh); cudaGetSymbolAddress((void**)&wvl, g_wvl);
    cudaGetSymbolAddress((void**)&wqh, g_wqh); cudaGetSymbolAddress((void**)&wql, g_wql);
    cudaGetSymbolAddress((void**)&wbh, g_wbh); cudaGetSymbolAddress((void**)&wbl, g_wbl);
    cudaGetSymbolAddress((void**)&woh, g_woh); cudaGetSymbolAddress((void**)&wol, g_wol);
    cudaGetSymbolAddress((void**)&k,  g_k);  cudaGetSymbolAddress((void**)&v,  g_v);
    cudaGetSymbolAddress((void**)&q,  g_q);  cudaGetSymbolAddress((void**)&bt, g_beta);
    cudaGetSymbolAddress((void**)&cellh, g_cellh);
    cudaGetSymbolAddress((void**)&celll, g_celll);

    cudaFuncSetAttribute(gemm_bf16<0>, cudaFuncAttributeMaxDynamicSharedMemorySize, SMEM_GB);
    cudaFuncSetAttribute(gemm_bf16<4>, cudaFuncAttributeMaxDynamicSharedMemorySize, SMEM_GB);
    cudaFuncSetAttribute(gemm_proj4,   cudaFuncAttributeMaxDynamicSharedMemorySize, SMEM_GB);

    const int M = MROWS;

    // 0. split fp32 operands into bf16 hi/lo planes
    split_kernel<<<(M * DD / 2) / 256, 256>>>((const float2*)x, xh, xl, M * DD / 2);
    split_kernel<<<(DD * DD / 2) / 256, 256>>>((const float2*)W_in, wih, wil, DD * DD / 2);
    split_kernel<<<(HN * DD / 2) / 256, 256>>>((const float2*)W_k, wkh, wkl, HN * DD / 2);
    split_kernel<<<(HN * DD / 2) / 256, 256>>>((const float2*)W_v, wvh, wvl, HN * DD / 2);
    split_kernel<<<(HN * DD / 2) / 256, 256>>>((const float2*)W_q, wqh, wql, HN * DD / 2);
    split_kernel<<<(HN * DD / 2) / 256, 256>>>((const float2*)W_beta, wbh, wbl, HN * DD / 2);
    split_kernel<<<(DD * HN / 2) / 256, 256>>>((const float2*)W_out, woh, wol, DD * HN / 2);

    // 1. xp = silu(x @ W_in^T) -> split planes (epi 4)
    gemm_bf16<4><<<dim3(DD / 128, M / 256), 256, SMEM_GB>>>(
        xh, xl, wih, wil, nullptr, xph, xpl, nullptr, DD, DD / 2);

    // 2. fused projections: k (normalized), v, q, beta
    ProjPtrs p;
    p.Wh[0] = wkh; p.Wl[0] = wkl; p.C[0] = k;
    p.Wh[1] = wvh; p.Wl[1] = wvl; p.C[1] = v;
    p.Wh[2] = wqh; p.Wl[2] = wql; p.C[2] = q;
    p.Wh[3] = wbh; p.Wl[3] = wbl; p.C[3] = bt;
    gemm_proj4<<<dim3(HN / 128, M / 256, 4), 256, SMEM_GB>>>(
        xph, xpl, p, b_beta, HN, DD / 2);

    // 3. sequential scan (writes cell as split bf16 planes)
    const size_t y_elems = (size_t)M * DD;
    const int writeS = (out_size >= (int)(y_elems + (size_t)BB * HH * NN * NN)) ? 1 : 0;
    scan_kernel<<<256, 128>>>(k, v, q, bt, cellh, celll, y + y_elems, writeS);

    // 4. y = cell @ W_out^T
    gemm_bf16<0><<<dim3(DD / 128, M / 256), 256, SMEM_GB>>>(
        (const unsigned*)cellh, (const unsigned*)celll, woh, wol,
        y, nullptr, nullptr, nullptr, DD, HN / 2);
}